// round 6
// baseline (speedup 1.0000x reference)
#include <cuda_runtime.h>
#include <cuda_bf16.h>
#include <cstdint>

#define TT 512
#define CC 64
#define NB 1024   // B*T
#define NCHUNK_BLKS 1280
#define NBLK 2560

// scratch (allocation-free rule: __device__ globals)
__device__ float g_kp[NB * CC];
__device__ float g_qp[NB * CC];
__device__ float g_v [NB * CC];
__device__ float g_logits[NB * TT];
__device__ __nv_bfloat16 g_Wt[64 * 128];   // W1p^T bf16 [n][k]
__device__ int g_cnt[NB];                  // per-row chunk counters (self-reset)
__device__ volatile int g_wt_ready;        // -> 8
__device__ volatile int g_pq_ready;        // -> 256
__device__ int g_done;                     // -> NBLK, resets the two above

// smem: As[128][136]bf16 34816@0, Wt[64][136]bf16 17408@34816,
//       W2_s 256@52224 ; winner aliases: ls 2048@0, red 1024@2048, rbuf@3072, flag@3104
// duty aliases (pre-Wt): xs 1024@34816, x1s 1024@35840
#define SMEM_BYTES 52736

__global__ __launch_bounds__(256, 4) void fused_kernel(
    const float* __restrict__ x,   const float* __restrict__ pos,
    const float* __restrict__ W1,  const float* __restrict__ b1,
    const float* __restrict__ Wv,  const float* __restrict__ bv,
    const float* __restrict__ pdist,
    const float* __restrict__ W2,  const float* __restrict__ b2,
    float* __restrict__ out)
{
    extern __shared__ char smem[];
    __nv_bfloat16* As = (__nv_bfloat16*)(smem);
    __nv_bfloat16* Wt = (__nv_bfloat16*)(smem + 34816);
    float* W2_s  = (float*)(smem + 52224);
    float* ls    = (float*)(smem);
    float* red   = (float*)(smem + 2048);
    float* rbuf  = (float*)(smem + 3072);
    int*   sflag = (int*)(smem + 3104);

    const int tid = threadIdx.x;
    const int bid = blockIdx.x;

    // ================= duty phase (wave-1 blocks) =================
    if (bid < 8) {
        // fill g_Wt: W1p^T -> bf16 [n][k]
        int base = bid * 1024 + tid;
#pragma unroll
        for (int r = 0; r < 4; r++) {
            int idx = base + r * 256;
            int n = idx >> 7, k = idx & 127;
            g_Wt[n * 128 + k] = __float2bfloat16_rn(W1[(128 + k) * 64 + n]);
        }
        __threadfence();
        __syncthreads();
        if (tid == 0) atomicAdd((int*)&g_wt_ready, 1);
    } else if (bid < 264) {
        // projections for 4 tokens
        float* xs  = (float*)(smem + 34816);
        float* x1s = xs + 256;
        const int t0 = (bid - 8) * 4;
        const int tl = tid >> 6;
        const int c  = tid & 63;
        {
            float xv = x[(t0 + tl) * 64 + c];
            xs [tid] = xv;
            x1s[tid] = xv + pos[(((t0 + tl) & (TT - 1)) * 64) + c];
        }
        __syncthreads();
        float ak = 0.f, aq = 0.f, av = 0.f;
#pragma unroll 8
        for (int k = 0; k < 64; k++) {
            float x1v = x1s[tl * 64 + k];
            float xv  = xs [tl * 64 + k];
            ak = fmaf(x1v, W1[k * 64 + c], ak);
            aq = fmaf(x1v, W1[(64 + k) * 64 + c], aq);
            av = fmaf(xv,  Wv[k * 64 + c], av);
        }
        const int bi2 = t0 + tl;
        g_kp[bi2 * 64 + c] = ak;
        g_qp[bi2 * 64 + c] = aq + b1[c];
        g_v [bi2 * 64 + c] = av + bv[c];
        __threadfence();
        __syncthreads();
        if (tid == 0) atomicAdd((int*)&g_pq_ready, 1);
        __syncthreads();   // xs region reused as Wt below
    }

    // ================= decode (b, i, ch) =================
    int z = bid;
    int b = 0;
    if (z >= NCHUNK_BLKS) { b = 1; z -= NCHUNK_BLKS; }
    int ch, i;
    if (z < 512)       { ch = 0; i = z; }
    else if (z < 896)  { ch = 1; i = 128 + (z - 512); }
    else if (z < 1152) { ch = 2; i = 256 + (z - 896); }
    else               { ch = 3; i = 384 + (z - 1152); }
    const int bi    = b * TT + i;
    const int jbase = ch << 7;
    const int imax  = i - jbase;
    const int nch   = (i >> 7) + 1;

    const int lane = tid & 31;
    const int w    = tid >> 5;
    const int g    = lane >> 2;
    const int tc   = lane & 3;
    const int wrow = w * 16;
    const bool active = (wrow <= imax);

    // ---- front-issue pdist DRAM loads (independent of Wt / kp / qp) ----
    if (active) {
        const int rmaxi = imax - wrow;
        const float4* src = (const float4*)(pdist + ((size_t)bi * TT + jbase) * 128);
#pragma unroll
        for (int r = 0; r < 16; r++) {
            if (r <= rmaxi) {
                int jloc = wrow + r;
                float4 vv = src[jloc * 32 + lane];
                __nv_bfloat162 lo = __floats2bfloat162_rn(vv.x, vv.y);
                __nv_bfloat162 hi = __floats2bfloat162_rn(vv.z, vv.w);
                uint2 u;
                u.x = *(uint32_t*)&lo;
                u.y = *(uint32_t*)&hi;
                *(uint2*)((char*)As + jloc * 272 + lane * 8) = u;
            }
        }
    }

    // ---- wait for g_Wt, then fill smem Wt ----
    if (tid == 0) { while (g_wt_ready != 8) __nanosleep(128); }
    __syncthreads();
    __threadfence();
#pragma unroll
    for (int r = 0; r < 4; r++) {
        int s = tid + r * 256;
        int n = s >> 4, k8 = s & 15;
        uint4 u = *(const uint4*)((const char*)g_Wt + n * 256 + k8 * 16);
        *(uint4*)((char*)Wt + n * 272 + k8 * 16) = u;
    }
    if (tid < 64) W2_s[tid] = W2[tid];
    __syncthreads();   // Wt ready + As rows visible block-wide

    if (active) {
        uint32_t As_u = (uint32_t)__cvta_generic_to_shared(As);
        uint32_t Wt_u = (uint32_t)__cvta_generic_to_shared(Wt);
        uint32_t a_base = As_u + (uint32_t)((wrow + (lane & 7) + ((lane >> 3) & 1) * 8) * 272
                                            + (lane >> 4) * 16);
        const int nrow  = (lane & 7) + ((lane >> 4) << 3);
        const int khalf = ((lane >> 3) & 1) * 8;
        uint32_t b_base = Wt_u + (uint32_t)((nrow * 136 + khalf) * 2);

        float acc[32];
#pragma unroll
        for (int zz = 0; zz < 32; zz++) acc[zz] = 0.f;

#pragma unroll
        for (int kt = 0; kt < 8; kt++) {
            uint32_t a0, a1, a2, a3;
            asm volatile("ldmatrix.sync.aligned.m8n8.x4.shared.b16 {%0,%1,%2,%3}, [%4];"
                         : "=r"(a0), "=r"(a1), "=r"(a2), "=r"(a3)
                         : "r"(a_base + kt * 32));
#pragma unroll
            for (int nt2 = 0; nt2 < 4; nt2++) {
                uint32_t r0, r1, r2, r3;
                asm volatile("ldmatrix.sync.aligned.m8n8.x4.shared.b16 {%0,%1,%2,%3}, [%4];"
                             : "=r"(r0), "=r"(r1), "=r"(r2), "=r"(r3)
                             : "r"(b_base + (uint32_t)(nt2 * 16 * 272 + kt * 32)));
                int nt = nt2 * 2;
                asm volatile(
                    "mma.sync.aligned.m16n8k16.row.col.f32.bf16.bf16.f32 "
                    "{%0,%1,%2,%3}, {%4,%5,%6,%7}, {%8,%9}, {%0,%1,%2,%3};"
                    : "+f"(acc[nt * 4 + 0]), "+f"(acc[nt * 4 + 1]),
                      "+f"(acc[nt * 4 + 2]), "+f"(acc[nt * 4 + 3])
                    : "r"(a0), "r"(a1), "r"(a2), "r"(a3), "r"(r0), "r"(r1));
                asm volatile(
                    "mma.sync.aligned.m16n8k16.row.col.f32.bf16.bf16.f32 "
                    "{%0,%1,%2,%3}, {%4,%5,%6,%7}, {%8,%9}, {%0,%1,%2,%3};"
                    : "+f"(acc[nt * 4 + 4]), "+f"(acc[nt * 4 + 5]),
                      "+f"(acc[nt * 4 + 6]), "+f"(acc[nt * 4 + 7])
                    : "r"(a0), "r"(a1), "r"(a2), "r"(a3), "r"(r2), "r"(r3));
            }
        }

        // ---- wait for kp/qp (per-warp spin), then fused epilogue ----
        if (lane == 0) { while (g_pq_ready != 256) __nanosleep(128); }
        __syncwarp();
        __threadfence();

        const int j0 = jbase + wrow + g;
        const int j1 = j0 + 8;
        const float* kp0 = g_kp + ((size_t)b * TT + j0) * 64;
        const float* kp1 = kp0 + 8 * 64;
        const float* qpr = g_qp + (size_t)bi * 64;
        float p0 = 0.f, p1 = 0.f;
#pragma unroll
        for (int nt = 0; nt < 8; nt++) {
            int c = nt * 8 + 2 * tc;
            float2 k0 = *(const float2*)(kp0 + c);
            float2 k1 = *(const float2*)(kp1 + c);
            float2 qv = *(const float2*)(qpr + c);
            float w20 = W2_s[c], w21 = W2_s[c + 1];
            float hh, h2, e, r;
            // gelu tanh-form: h - h / (1 + 2^(h*(c1*h^2 + c0)))  (log2e folded)
            hh = acc[nt * 4 + 0] + qv.x + k0.x;
            h2 = hh * hh;
            asm("ex2.approx.f32 %0, %1;" : "=f"(e) : "f"(hh * fmaf(0.10294324f, h2, 2.3022087f)));
            r  = __fdividef(hh, e + 1.f);
            p0 = fmaf(w20, hh - r, p0);
            hh = acc[nt * 4 + 1] + qv.y + k0.y;
            h2 = hh * hh;
            asm("ex2.approx.f32 %0, %1;" : "=f"(e) : "f"(hh * fmaf(0.10294324f, h2, 2.3022087f)));
            r  = __fdividef(hh, e + 1.f);
            p0 = fmaf(w21, hh - r, p0);
            hh = acc[nt * 4 + 2] + qv.x + k1.x;
            h2 = hh * hh;
            asm("ex2.approx.f32 %0, %1;" : "=f"(e) : "f"(hh * fmaf(0.10294324f, h2, 2.3022087f)));
            r  = __fdividef(hh, e + 1.f);
            p1 = fmaf(w20, hh - r, p1);
            hh = acc[nt * 4 + 3] + qv.y + k1.y;
            h2 = hh * hh;
            asm("ex2.approx.f32 %0, %1;" : "=f"(e) : "f"(hh * fmaf(0.10294324f, h2, 2.3022087f)));
            r  = __fdividef(hh, e + 1.f);
            p1 = fmaf(w21, hh - r, p1);
        }
        p0 += __shfl_xor_sync(0xffffffffu, p0, 1);
        p0 += __shfl_xor_sync(0xffffffffu, p0, 2);
        p1 += __shfl_xor_sync(0xffffffffu, p1, 1);
        p1 += __shfl_xor_sync(0xffffffffu, p1, 2);
        if (tc == 0) {
            g_logits[bi * TT + j0] = p0;
            g_logits[bi * TT + j1] = p1;
        }
    }

    // ================= winner election =================
    __syncthreads();
    if (tid == 0) {
        __threadfence();
        int old = atomicAdd(&g_cnt[bi], 1);
        if (old == nch - 1) {
            *sflag = 1;
            g_cnt[bi] = 0;
        } else {
            *sflag = 0;
        }
    }
    __syncthreads();
    if (tid == 0) {
        int od = atomicAdd(&g_done, 1);
        if (od == NBLK - 1) {        // last block: reset spin counters
            g_done = 0;
            g_wt_ready = 0;
            g_pq_ready = 0;
        }
    }
    if (!*sflag) return;
    __threadfence();

    // ================= winner: softmax + wei@v =================
    const float b2v = b2[0];
    float lmax = -1e30f;
    for (int j = tid; j <= i; j += 256) {
        float l = (__ldcg(&g_logits[bi * TT + j]) + b2v) * 0.125f;
        ls[j] = l;
        lmax = fmaxf(lmax, l);
    }
#pragma unroll
    for (int o = 16; o; o >>= 1) lmax = fmaxf(lmax, __shfl_xor_sync(0xffffffffu, lmax, o));
    if (lane == 0) rbuf[w] = lmax;
    __syncthreads();
    float gmax = rbuf[0];
#pragma unroll
    for (int zz = 1; zz < 8; zz++) gmax = fmaxf(gmax, rbuf[zz]);
    __syncthreads();

    float lsum = 0.f;
    for (int j = tid; j <= i; j += 256) {
        float p = __expf(ls[j] - gmax);
        ls[j] = p;
        lsum += p;
    }
#pragma unroll
    for (int o = 16; o; o >>= 1) lsum += __shfl_xor_sync(0xffffffffu, lsum, o);
    if (lane == 0) rbuf[w] = lsum;
    __syncthreads();
    float tot = rbuf[0];
#pragma unroll
    for (int zz = 1; zz < 8; zz++) tot += rbuf[zz];
    const float inv = 1.f / tot;
    __syncthreads();

    const int h = tid & 63, q = tid >> 6;
    const float* vb = g_v + (size_t)b * TT * 64;
    float a0 = 0.f;
#pragma unroll 4
    for (int j = q; j <= i; j += 4)
        a0 = fmaf(ls[j], vb[j * 64 + h], a0);
    red[q * 64 + h] = a0;
    __syncthreads();
    if (tid < 64) {
        float rr = red[tid] + red[tid + 64] + red[tid + 128] + red[tid + 192];
        out[bi * 64 + tid] = rr * inv;
    }
}

// ---------------- launcher ----------------
extern "C" void kernel_launch(void* const* d_in, const int* in_sizes, int n_in,
                              void* d_out, int out_size)
{
    const float* x     = (const float*)d_in[0];
    const float* pos   = (const float*)d_in[1];
    const float* pdist = (const float*)d_in[2];
    const float* W1    = (const float*)d_in[3];
    const float* b1    = (const float*)d_in[4];
    const float* W2    = (const float*)d_in[5];
    const float* b2    = (const float*)d_in[6];
    const float* Wv    = (const float*)d_in[7];
    const float* bv    = (const float*)d_in[8];
    float* out = (float*)d_out;

    cudaFuncSetAttribute(fused_kernel, cudaFuncAttributeMaxDynamicSharedMemorySize, SMEM_BYTES);
    fused_kernel<<<NBLK, 256, SMEM_BYTES>>>(x, pos, W1, b1, Wv, bv, pdist, W2, b2, out);
}

// round 7
// speedup vs baseline: 1.2355x; 1.2355x over previous
#include <cuda_runtime.h>
#include <cuda_bf16.h>
#include <cstdint>

#define TT 512
#define CC 64
#define NB 1024   // B*T
#define NCHUNK_BLKS 1280

// scratch (allocation-free rule: __device__ globals)
__device__ float g_kp[NB * CC];
__device__ float g_qp[NB * CC];           // qp + b1 folded
__device__ float g_v [NB * CC];
__device__ float g_logits[NB * TT];
__device__ __nv_bfloat16 g_Wt[64 * 128];  // W1p^T bf16 [n][k]
__device__ int g_cnt[NB];                 // per-row chunk counters (self-reset)

// ---------------- kernel 1: projections + W1p transpose ----------------
// blocks 0..511: 2 tokens, 384 threads = 2tok x 3mat x 64c (one output each)
// blocks 512..519: g_Wt transpose fill
__global__ __launch_bounds__(384) void prep_kernel(
    const float* __restrict__ x, const float* __restrict__ pos,
    const float* __restrict__ W1, const float* __restrict__ b1,
    const float* __restrict__ Wv, const float* __restrict__ bv)
{
    const int tid = threadIdx.x;
    const int bid = blockIdx.x;

    if (bid >= 512) {
        int base = (bid - 512) * 1024;
#pragma unroll
        for (int r = 0; r < 3; r++) {
            int idx = tid + r * 384;
            if (idx < 1024) {
                int e = base + idx;             // 0..8191
                int n = e >> 7, k = e & 127;
                g_Wt[n * 128 + k] = __float2bfloat16_rn(W1[(128 + k) * 64 + n]);
            }
        }
        return;
    }

    __shared__ float xs[128], x1s[128];
    const int t0 = bid * 2;
    if (tid < 128) {
        int tl = tid >> 6, c = tid & 63;
        float xv = x[(t0 + tl) * 64 + c];
        xs [tid] = xv;
        x1s[tid] = xv + pos[(((t0 + tl) & (TT - 1)) * 64) + c];
    }
    __syncthreads();

    const int tok = tid / 192;        // 0..1
    const int m   = (tid % 192) >> 6; // 0 kp, 1 qp, 2 v
    const int c   = tid & 63;
    const int bi  = t0 + tok;

    const float* Wp = (m == 0) ? W1 : (m == 1) ? (W1 + 4096) : Wv;
    const float* in = (m == 2) ? (xs + tok * 64) : (x1s + tok * 64);

    float a = 0.f;
#pragma unroll 8
    for (int k = 0; k < 64; k++)
        a = fmaf(in[k], Wp[k * 64 + c], a);

    if (m == 0)      g_kp[bi * 64 + c] = a;
    else if (m == 1) g_qp[bi * 64 + c] = a + b1[c];
    else             g_v [bi * 64 + c] = a + bv[c];
}

// ---------------- kernel 2: (b,i,chunk) blocks + fused winner softmax/AV ----------------
// smem bytes: As[128][136]bf16 34816@0, Wt[64][136]bf16 17408@34816,
//             qp_s 256@52224, W2_s 256@52480
// winner aliases (As region): ls 2048@0, red 4096@2048, rbuf 32@6144, flag@6176
#define SMEM_BYTES 52736

__global__ __launch_bounds__(256, 4) void attn_kernel(
    const float* __restrict__ pdist,
    const float* __restrict__ W2,
    const float* __restrict__ b2,
    float* __restrict__ out)
{
    extern __shared__ char smem[];
    __nv_bfloat16* As = (__nv_bfloat16*)(smem);
    __nv_bfloat16* Wt = (__nv_bfloat16*)(smem + 34816);
    float* qp_s  = (float*)(smem + 52224);
    float* W2_s  = (float*)(smem + 52480);
    float* ls    = (float*)(smem);
    float* red   = (float*)(smem + 2048);
    float* rbuf  = (float*)(smem + 6144);
    int*   sflag = (int*)(smem + 6176);

    const int tid = threadIdx.x;

    // decode (b, i, ch)
    int z = blockIdx.x;
    int b = 0;
    if (z >= NCHUNK_BLKS) { b = 1; z -= NCHUNK_BLKS; }
    int ch, i;
    if (z < 512)       { ch = 0; i = z; }
    else if (z < 896)  { ch = 1; i = 128 + (z - 512); }
    else if (z < 1152) { ch = 2; i = 256 + (z - 896); }
    else               { ch = 3; i = 384 + (z - 1152); }
    const int bi    = b * TT + i;
    const int jbase = ch << 7;
    const int imax  = i - jbase;
    const int nch   = (i >> 7) + 1;

    // ---- Wt fill + qp/W2 staging ----
#pragma unroll
    for (int r = 0; r < 4; r++) {
        int s = tid + r * 256;
        int n = s >> 4, k8 = s & 15;
        uint4 u = *(const uint4*)((const char*)g_Wt + n * 256 + k8 * 16);
        *(uint4*)((char*)Wt + n * 272 + k8 * 16) = u;
    }
    if (tid < 64) {
        qp_s[tid] = g_qp[bi * 64 + tid];
        W2_s[tid] = W2[tid];
    }
    __syncthreads();

    const int lane = tid & 31;
    const int w    = tid >> 5;
    const int g    = lane >> 2;
    const int tc   = lane & 3;
    const int wrow = w * 16;

    if (wrow <= imax) {
        const int rmaxi = imax - wrow;

        // per-warp load of its own 16 rows (fp32 -> bf16, padded)
        const float4* src = (const float4*)(pdist + ((size_t)bi * TT + jbase) * 128);
#pragma unroll
        for (int r = 0; r < 16; r++) {
            if (r <= rmaxi) {
                int jloc = wrow + r;
                float4 vv = src[jloc * 32 + lane];
                __nv_bfloat162 lo = __floats2bfloat162_rn(vv.x, vv.y);
                __nv_bfloat162 hi = __floats2bfloat162_rn(vv.z, vv.w);
                uint2 u;
                u.x = *(uint32_t*)&lo;
                u.y = *(uint32_t*)&hi;
                *(uint2*)((char*)As + jloc * 272 + lane * 8) = u;
            }
        }
        __syncwarp();

        uint32_t As_u = (uint32_t)__cvta_generic_to_shared(As);
        uint32_t Wt_u = (uint32_t)__cvta_generic_to_shared(Wt);
        uint32_t a_base = As_u + (uint32_t)((wrow + (lane & 7) + ((lane >> 3) & 1) * 8) * 272
                                            + (lane >> 4) * 16);
        const int nrow  = (lane & 7) + ((lane >> 4) << 3);
        const int khalf = ((lane >> 3) & 1) * 8;
        uint32_t b_base = Wt_u + (uint32_t)((nrow * 136 + khalf) * 2);

        float acc[32];
#pragma unroll
        for (int zz = 0; zz < 32; zz++) acc[zz] = 0.f;

#pragma unroll
        for (int kt = 0; kt < 8; kt++) {
            uint32_t a0, a1, a2, a3;
            asm volatile("ldmatrix.sync.aligned.m8n8.x4.shared.b16 {%0,%1,%2,%3}, [%4];"
                         : "=r"(a0), "=r"(a1), "=r"(a2), "=r"(a3)
                         : "r"(a_base + kt * 32));
#pragma unroll
            for (int nt2 = 0; nt2 < 4; nt2++) {
                uint32_t r0, r1, r2, r3;
                asm volatile("ldmatrix.sync.aligned.m8n8.x4.shared.b16 {%0,%1,%2,%3}, [%4];"
                             : "=r"(r0), "=r"(r1), "=r"(r2), "=r"(r3)
                             : "r"(b_base + (uint32_t)(nt2 * 16 * 272 + kt * 32)));
                int nt = nt2 * 2;
                asm volatile(
                    "mma.sync.aligned.m16n8k16.row.col.f32.bf16.bf16.f32 "
                    "{%0,%1,%2,%3}, {%4,%5,%6,%7}, {%8,%9}, {%0,%1,%2,%3};"
                    : "+f"(acc[nt * 4 + 0]), "+f"(acc[nt * 4 + 1]),
                      "+f"(acc[nt * 4 + 2]), "+f"(acc[nt * 4 + 3])
                    : "r"(a0), "r"(a1), "r"(a2), "r"(a3), "r"(r0), "r"(r1));
                asm volatile(
                    "mma.sync.aligned.m16n8k16.row.col.f32.bf16.bf16.f32 "
                    "{%0,%1,%2,%3}, {%4,%5,%6,%7}, {%8,%9}, {%0,%1,%2,%3};"
                    : "+f"(acc[nt * 4 + 4]), "+f"(acc[nt * 4 + 5]),
                      "+f"(acc[nt * 4 + 6]), "+f"(acc[nt * 4 + 7])
                    : "r"(a0), "r"(a1), "r"(a2), "r"(a3), "r"(r2), "r"(r3));
            }
        }

        // fused epilogue: +qp'(smem)+kp, gelu (ex2), dot W2
        const int j0 = jbase + wrow + g;
        const int j1 = j0 + 8;
        const float* kp0 = g_kp + ((size_t)b * TT + j0) * 64;
        const float* kp1 = kp0 + 8 * 64;
        float p0 = 0.f, p1 = 0.f;
#pragma unroll
        for (int nt = 0; nt < 8; nt++) {
            int c = nt * 8 + 2 * tc;
            float2 k0 = *(const float2*)(kp0 + c);
            float2 k1 = *(const float2*)(kp1 + c);
            float2 qv = *(const float2*)(qp_s + c);
            float w20 = W2_s[c], w21 = W2_s[c + 1];
            float hh, h2, e, r;
            hh = acc[nt * 4 + 0] + qv.x + k0.x;
            h2 = hh * hh;
            asm("ex2.approx.f32 %0, %1;" : "=f"(e) : "f"(hh * fmaf(0.10294324f, h2, 2.3022087f)));
            r  = __fdividef(hh, e + 1.f);
            p0 = fmaf(w20, hh - r, p0);
            hh = acc[nt * 4 + 1] + qv.y + k0.y;
            h2 = hh * hh;
            asm("ex2.approx.f32 %0, %1;" : "=f"(e) : "f"(hh * fmaf(0.10294324f, h2, 2.3022087f)));
            r  = __fdividef(hh, e + 1.f);
            p0 = fmaf(w21, hh - r, p0);
            hh = acc[nt * 4 + 2] + qv.x + k1.x;
            h2 = hh * hh;
            asm("ex2.approx.f32 %0, %1;" : "=f"(e) : "f"(hh * fmaf(0.10294324f, h2, 2.3022087f)));
            r  = __fdividef(hh, e + 1.f);
            p1 = fmaf(w20, hh - r, p1);
            hh = acc[nt * 4 + 3] + qv.y + k1.y;
            h2 = hh * hh;
            asm("ex2.approx.f32 %0, %1;" : "=f"(e) : "f"(hh * fmaf(0.10294324f, h2, 2.3022087f)));
            r  = __fdividef(hh, e + 1.f);
            p1 = fmaf(w21, hh - r, p1);
        }
        p0 += __shfl_xor_sync(0xffffffffu, p0, 1);
        p0 += __shfl_xor_sync(0xffffffffu, p0, 2);
        p1 += __shfl_xor_sync(0xffffffffu, p1, 1);
        p1 += __shfl_xor_sync(0xffffffffu, p1, 2);
        if (tc == 0) {
            g_logits[bi * TT + j0] = p0;
            g_logits[bi * TT + j1] = p1;
        }
    }

    // ---- winner election ----
    __syncthreads();
    if (tid == 0) {
        __threadfence();
        int old = atomicAdd(&g_cnt[bi], 1);
        if (old == nch - 1) {
            *sflag = 1;
            g_cnt[bi] = 0;   // self-reset for graph replay
        } else {
            *sflag = 0;
        }
    }
    __syncthreads();
    if (!*sflag) return;
    __threadfence();  // acquire

    // ---- winner: softmax ----
    const float b2v = b2[0];
    float lmax = -1e30f;
    for (int j = tid; j <= i; j += 256) {
        float l = (__ldcg(&g_logits[bi * TT + j]) + b2v) * 0.125f;
        ls[j] = l;
        lmax = fmaxf(lmax, l);
    }
#pragma unroll
    for (int o = 16; o; o >>= 1) lmax = fmaxf(lmax, __shfl_xor_sync(0xffffffffu, lmax, o));
    if (lane == 0) rbuf[w] = lmax;
    __syncthreads();
    float gmax = rbuf[0];
#pragma unroll
    for (int zz = 1; zz < 8; zz++) gmax = fmaxf(gmax, rbuf[zz]);
    __syncthreads();

    float lsum = 0.f;
    for (int j = tid; j <= i; j += 256) {
        float p = __expf(ls[j] - gmax);
        ls[j] = p;
        lsum += p;
    }
#pragma unroll
    for (int o = 16; o; o >>= 1) lsum += __shfl_xor_sync(0xffffffffu, lsum, o);
    if (lane == 0) rbuf[w] = lsum;
    __syncthreads();
    float tot = rbuf[0];
#pragma unroll
    for (int zz = 1; zz < 8; zz++) tot += rbuf[zz];
    const float inv = 1.f / tot;
    __syncthreads();

    // ---- winner: wei@v, vectorized float4 ----
    {
        const int hg = tid & 15;          // col group (4 floats)
        const int js = tid >> 4;          // 0..15 j-slot
        const float4* v4 = (const float4*)(g_v + (size_t)b * TT * 64);
        float4 a4 = make_float4(0.f, 0.f, 0.f, 0.f);
#pragma unroll 4
        for (int j = js; j <= i; j += 16) {
            float wei = ls[j];
            float4 vv = v4[j * 16 + hg];
            a4.x = fmaf(wei, vv.x, a4.x);
            a4.y = fmaf(wei, vv.y, a4.y);
            a4.z = fmaf(wei, vv.z, a4.z);
            a4.w = fmaf(wei, vv.w, a4.w);
        }
        *(float4*)(red + js * 64 + hg * 4) = a4;
        __syncthreads();
        if (tid < 64) {
            float r = 0.f;
#pragma unroll
            for (int s = 0; s < 16; s++) r += red[s * 64 + tid];
            out[bi * 64 + tid] = r * inv;
        }
    }
}

// ---------------- launcher ----------------
extern "C" void kernel_launch(void* const* d_in, const int* in_sizes, int n_in,
                              void* d_out, int out_size)
{
    const float* x     = (const float*)d_in[0];
    const float* pos   = (const float*)d_in[1];
    const float* pdist = (const float*)d_in[2];
    const float* W1    = (const float*)d_in[3];
    const float* b1    = (const float*)d_in[4];
    const float* W2    = (const float*)d_in[5];
    const float* b2    = (const float*)d_in[6];
    const float* Wv    = (const float*)d_in[7];
    const float* bv    = (const float*)d_in[8];
    float* out = (float*)d_out;

    cudaFuncSetAttribute(attn_kernel, cudaFuncAttributeMaxDynamicSharedMemorySize, SMEM_BYTES);

    prep_kernel<<<520, 384>>>(x, pos, W1, b1, Wv, bv);
    attn_kernel<<<2 * NCHUNK_BLKS, 256, SMEM_BYTES>>>(pdist, W2, b2, out);
}